// round 6
// baseline (speedup 1.0000x reference)
#include <cuda_runtime.h>
#include <math.h>

// ---------------- problem constants ----------------
#define MROWS 4096            // B*T*N rows
#define DDIM  1152
#define NHEAD 16
#define HDIM  72
#define IDIM  4304
#define NPATCH 1024
#define KCONV 588             // 14*14*3
#define NLAYER 4

// ---------------- scratch (device globals; no allocations allowed) ----------
__device__ float g_x   [(size_t)MROWS*DDIM];
__device__ float g_h   [(size_t)MROWS*DDIM];
__device__ float g_q   [(size_t)MROWS*DDIM];
__device__ float g_k   [(size_t)MROWS*DDIM];
__device__ float g_v   [(size_t)MROWS*DDIM];
__device__ float g_attn[(size_t)MROWS*DDIM];
__device__ float g_mlp [(size_t)MROWS*IDIM];
__device__ float g_scor[(size_t)64*1024*1024];   // 64 (b,h) x 1024 x 1024
__device__ float g_col [(size_t)MROWS*KCONV];

// ---------------- im2col (stride == kernel, non-overlapping) ----------------
__global__ void im2col_k(const float* __restrict__ img, float* __restrict__ col) {
    int idx = blockIdx.x * blockDim.x + threadIdx.x;   // over 4096*588
    if (idx >= MROWS * KCONV) return;
    int p = idx / KCONV, j = idx % KCONV;
    int im = p >> 10;            // image 0..3
    int pr = (p >> 5) & 31;      // patch row
    int pc = p & 31;             // patch col
    int c  = j % 3;
    int t  = j / 3;
    int kx = t % 14, ky = t / 14;
    int y = pr * 14 + ky, x = pc * 14 + kx;
    col[idx] = img[(((size_t)im * 448 + y) * 448 + x) * 3 + c];
}

// ---------------- reductions ----------------
__device__ __forceinline__ float warp_sum(float v) {
    #pragma unroll
    for (int o = 16; o; o >>= 1) v += __shfl_xor_sync(0xffffffffu, v, o);
    return v;
}
__device__ __forceinline__ float warp_max(float v) {
    #pragma unroll
    for (int o = 16; o; o >>= 1) v = fmaxf(v, __shfl_xor_sync(0xffffffffu, v, o));
    return v;
}

// ---------------- layernorm: one block (256 thr) per row of length 1152 -----
__global__ void layernorm_k(const float* __restrict__ in, float* __restrict__ out,
                            const float* __restrict__ g, const float* __restrict__ b) {
    size_t row = blockIdx.x;
    const float* x = in + row * DDIM;
    float s = 0.f, s2 = 0.f;
    for (int i = threadIdx.x; i < DDIM; i += 256) { float v = x[i]; s += v; s2 += v * v; }
    __shared__ float sh0[8], sh1[8];
    s = warp_sum(s); s2 = warp_sum(s2);
    int w = threadIdx.x >> 5, l = threadIdx.x & 31;
    if (!l) { sh0[w] = s; sh1[w] = s2; }
    __syncthreads();
    if (w == 0) {
        float a = (l < 8) ? sh0[l] : 0.f;
        float c = (l < 8) ? sh1[l] : 0.f;
        a = warp_sum(a); c = warp_sum(c);
        if (!l) { sh0[0] = a; sh1[0] = c; }
    }
    __syncthreads();
    float mu  = sh0[0] * (1.f / DDIM);
    float var = sh1[0] * (1.f / DDIM) - mu * mu;
    float inv = rsqrtf(var + 1e-6f);
    float* o = out + row * DDIM;
    for (int i = threadIdx.x; i < DDIM; i += 256)
        o[i] = (x[i] - mu) * inv * g[i] + b[i];
}

// ---------------- softmax: one block (256 thr) per row of length 1024 -------
__global__ void softmax_k(float* __restrict__ s) {
    size_t row = blockIdx.x;
    float* p = s + row * 1024;
    __shared__ float sh[8];
    int w = threadIdx.x >> 5, l = threadIdx.x & 31;

    float mx = -1e30f;
    for (int i = threadIdx.x; i < 1024; i += 256) mx = fmaxf(mx, p[i]);
    mx = warp_max(mx);
    if (!l) sh[w] = mx;
    __syncthreads();
    if (w == 0) { float a = (l < 8) ? sh[l] : -1e30f; a = warp_max(a); if (!l) sh[0] = a; }
    __syncthreads();
    mx = sh[0];
    __syncthreads();

    float sum = 0.f;
    for (int i = threadIdx.x; i < 1024; i += 256) {
        float e = __expf(p[i] - mx);
        p[i] = e; sum += e;
    }
    sum = warp_sum(sum);
    if (!l) sh[w] = sum;
    __syncthreads();
    if (w == 0) { float a = (l < 8) ? sh[l] : 0.f; a = warp_sum(a); if (!l) sh[0] = a; }
    __syncthreads();
    float inv = 1.f / sh[0];
    for (int i = threadIdx.x; i < 1024; i += 256) p[i] *= inv;
}

// ---------------- generic fp32 GEMM, 128x128x8, 8x8 per thread --------------
// C[M,N] = alpha * A[M,K] * op(B) (+ bias[n]) (+ posemb) (gelu) (+ resid)
// TRANSB: op(B)(k,n) = B[n*ldb + k]  (else B[k*ldb + n])
// batch_mode: 0 none; 1 scores (A=Q,B=K per (b,h), C per z);
//             2 PV (A=probs per z, B=V per (b,h), C per (b,h))
#define BM 128
#define BN 128
#define BK 8
#define FLAG_GELU 1

template<bool TRANSB>
__global__ void __launch_bounds__(256)
sgemm_k(const float* __restrict__ A, const float* __restrict__ B, float* __restrict__ C,
        int M, int N, int K, int lda, int ldb, int ldc,
        const float* __restrict__ bias, const float* __restrict__ resid,
        const float* __restrict__ posemb, float alpha, int flags, int bmode) {
    int z = blockIdx.z;
    if (bmode == 1) {
        int bb = z >> 4, hh = z & 15;
        size_t qk = (size_t)bb * 1024 * DDIM + (size_t)hh * HDIM;
        A += qk; B += qk; C += (size_t)z * 1024 * 1024;
    } else if (bmode == 2) {
        int bb = z >> 4, hh = z & 15;
        size_t vo = (size_t)bb * 1024 * DDIM + (size_t)hh * HDIM;
        A += (size_t)z * 1024 * 1024; B += vo; C += vo;
        if (resid) resid += vo;
    }

    __shared__ float As[BK][BM];
    __shared__ float Bs[BK][BN];

    int bm = blockIdx.y * BM, bn = blockIdx.x * BN;
    int tid = threadIdx.x;
    int ty = tid >> 4, tx = tid & 15;
    int mrow = ty * 8, ncol = tx * 8;

    float acc[8][8];
    #pragma unroll
    for (int i = 0; i < 8; i++)
        #pragma unroll
        for (int j = 0; j < 8; j++) acc[i][j] = 0.f;

    for (int k0 = 0; k0 < K; k0 += BK) {
        // --- load A tile (128 x 8), one float4 per thread, transposed into As
        {
            int r  = tid >> 1;
            int kq = (tid & 1) * 4;
            int gm = bm + r, gk = k0 + kq;
            float4 v = make_float4(0.f, 0.f, 0.f, 0.f);
            if (gm < M && gk < K)
                v = *(const float4*)(A + (size_t)gm * lda + gk);
            As[kq + 0][r] = v.x; As[kq + 1][r] = v.y;
            As[kq + 2][r] = v.z; As[kq + 3][r] = v.w;
        }
        // --- load B tile (8 x 128)
        if (!TRANSB) {
            int r = tid >> 5;
            int c = (tid & 31) * 4;
            int gk = k0 + r, gn = bn + c;
            float4 v = make_float4(0.f, 0.f, 0.f, 0.f);
            if (gk < K && gn < N)   // N,K multiples of 4 -> whole float4 valid
                v = *(const float4*)(B + (size_t)gk * ldb + gn);
            *(float4*)&Bs[r][c] = v;
        } else {
            int n  = tid >> 1;
            int kq = (tid & 1) * 4;
            int gn = bn + n, gk = k0 + kq;
            float4 v = make_float4(0.f, 0.f, 0.f, 0.f);
            if (gn < N && gk < K)
                v = *(const float4*)(B + (size_t)gn * ldb + gk);
            Bs[kq + 0][n] = v.x; Bs[kq + 1][n] = v.y;
            Bs[kq + 2][n] = v.z; Bs[kq + 3][n] = v.w;
        }
        __syncthreads();

        #pragma unroll
        for (int kk = 0; kk < BK; kk++) {
            float a[8], bb[8];
            *(float4*)&a[0]  = *(float4*)&As[kk][mrow];
            *(float4*)&a[4]  = *(float4*)&As[kk][mrow + 4];
            *(float4*)&bb[0] = *(float4*)&Bs[kk][ncol];
            *(float4*)&bb[4] = *(float4*)&Bs[kk][ncol + 4];
            #pragma unroll
            for (int i = 0; i < 8; i++)
                #pragma unroll
                for (int j = 0; j < 8; j++)
                    acc[i][j] = fmaf(a[i], bb[j], acc[i][j]);
        }
        __syncthreads();
    }

    // --- epilogue
    const float GC = 0.7978845608028654f;   // sqrt(2/pi)
    #pragma unroll
    for (int i = 0; i < 8; i++) {
        int gm = bm + mrow + i;
        if (gm >= M) continue;
        #pragma unroll
        for (int j = 0; j < 8; j++) {
            int gn = bn + ncol + j;
            if (gn >= N) continue;
            float v = acc[i][j] * alpha;
            if (bias)   v += bias[gn];
            if (posemb) v += posemb[(size_t)(gm & (NPATCH - 1)) * DDIM + gn];
            if (flags & FLAG_GELU) {
                float t = v;
                v = 0.5f * t * (1.f + tanhf(GC * (t + 0.044715f * t * t * t)));
            }
            if (resid)  v += resid[(size_t)gm * ldc + gn];
            C[(size_t)gm * ldc + gn] = v;
        }
    }
}

// ---------------- host-side helpers ----------------
static void gemm(const float* A, const float* B, float* C,
                 int M, int N, int K, int lda, int ldb, int ldc,
                 const float* bias, const float* resid, const float* posemb,
                 float alpha, int flags, int bmode, int Z, bool transb) {
    dim3 grid((N + BN - 1) / BN, (M + BM - 1) / BM, Z);
    if (transb)
        sgemm_k<true ><<<grid, 256>>>(A, B, C, M, N, K, lda, ldb, ldc,
                                      bias, resid, posemb, alpha, flags, bmode);
    else
        sgemm_k<false><<<grid, 256>>>(A, B, C, M, N, K, lda, ldb, ldc,
                                      bias, resid, posemb, alpha, flags, bmode);
}

extern "C" void kernel_launch(void* const* d_in, const int* in_sizes, int n_in,
                              void* d_out, int out_size) {
    const float* images = (const float*)d_in[0];
    const float* conv_w = (const float*)d_in[1];
    const float* conv_b = (const float*)d_in[2];
    const float* posemb = (const float*)d_in[3];
    const float* ln1_g  = (const float*)d_in[4];
    const float* ln1_b  = (const float*)d_in[5];
    const float* Wq     = (const float*)d_in[6];
    const float* bq     = (const float*)d_in[7];
    const float* Wk     = (const float*)d_in[8];
    const float* bk     = (const float*)d_in[9];
    const float* Wv     = (const float*)d_in[10];
    const float* bv     = (const float*)d_in[11];
    const float* Wo     = (const float*)d_in[12];
    const float* bo     = (const float*)d_in[13];
    const float* ln2_g  = (const float*)d_in[14];
    const float* ln2_b  = (const float*)d_in[15];
    const float* W1     = (const float*)d_in[16];
    const float* b1     = (const float*)d_in[17];
    const float* W2     = (const float*)d_in[18];
    const float* b2     = (const float*)d_in[19];
    const float* lnf_g  = (const float*)d_in[20];
    const float* lnf_b  = (const float*)d_in[21];
    float* out = (float*)d_out;

    float *x, *h, *q, *k, *v, *attn, *mlp, *scor, *col;
    cudaGetSymbolAddress((void**)&x,    g_x);
    cudaGetSymbolAddress((void**)&h,    g_h);
    cudaGetSymbolAddress((void**)&q,    g_q);
    cudaGetSymbolAddress((void**)&k,    g_k);
    cudaGetSymbolAddress((void**)&v,    g_v);
    cudaGetSymbolAddress((void**)&attn, g_attn);
    cudaGetSymbolAddress((void**)&mlp,  g_mlp);
    cudaGetSymbolAddress((void**)&scor, g_scor);
    cudaGetSymbolAddress((void**)&col,  g_col);

    const float scale = 1.f / sqrtf((float)HDIM);

    // 1) patch embedding: im2col + GEMM (+conv_b +pos_emb) -> x
    {
        int tot = MROWS * KCONV;
        im2col_k<<<(tot + 255) / 256, 256>>>(images, col);
        gemm(col, conv_w, x, MROWS, DDIM, KCONV, KCONV, DDIM, DDIM,
             conv_b, nullptr, posemb, 1.f, 0, 0, 1, false);
    }

    // 2) transformer layers
    for (int l = 0; l < NLAYER; l++) {
        const float* wq = Wq + (size_t)l * DDIM * DDIM;
        const float* wk = Wk + (size_t)l * DDIM * DDIM;
        const float* wv = Wv + (size_t)l * DDIM * DDIM;
        const float* wo = Wo + (size_t)l * DDIM * DDIM;
        const float* w1 = W1 + (size_t)l * DDIM * IDIM;
        const float* w2 = W2 + (size_t)l * IDIM * DDIM;

        layernorm_k<<<MROWS, 256>>>(x, h, ln1_g + l * DDIM, ln1_b + l * DDIM);

        gemm(h, wq, q, MROWS, DDIM, DDIM, DDIM, DDIM, DDIM,
             bq + l * DDIM, nullptr, nullptr, 1.f, 0, 0, 1, false);
        gemm(h, wk, k, MROWS, DDIM, DDIM, DDIM, DDIM, DDIM,
             bk + l * DDIM, nullptr, nullptr, 1.f, 0, 0, 1, false);
        gemm(h, wv, v, MROWS, DDIM, DDIM, DDIM, DDIM, DDIM,
             bv + l * DDIM, nullptr, nullptr, 1.f, 0, 0, 1, false);

        // scores[z] = scale * Q K^T   (z = b*16 + h, 64 batches)
        gemm(q, k, scor, 1024, 1024, HDIM, DDIM, DDIM, 1024,
             nullptr, nullptr, nullptr, scale, 0, 1, 64, true);

        softmax_k<<<64 * 1024, 256>>>(scor);

        // attn[z] = P V
        gemm(scor, v, attn, 1024, HDIM, 1024, 1024, DDIM, DDIM,
             nullptr, nullptr, nullptr, 1.f, 0, 2, 64, false);

        // x = x + attn @ Wo + bo
        gemm(attn, wo, x, MROWS, DDIM, DDIM, DDIM, DDIM, DDIM,
             bo + l * DDIM, x, nullptr, 1.f, 0, 0, 1, false);

        layernorm_k<<<MROWS, 256>>>(x, h, ln2_g + l * DDIM, ln2_b + l * DDIM);

        // mlp = gelu(h @ W1 + b1)
        gemm(h, w1, mlp, MROWS, IDIM, DDIM, DDIM, IDIM, IDIM,
             b1 + l * IDIM, nullptr, nullptr, 1.f, FLAG_GELU, 0, 1, false);

        // x = x + mlp @ W2 + b2
        gemm(mlp, w2, x, MROWS, DDIM, IDIM, IDIM, DDIM, DDIM,
             b2 + l * DDIM, x, nullptr, 1.f, 0, 0, 1, false);
    }

    // 3) final layernorm -> d_out ([2,2,1024,1152] is row-major [4096,1152])
    layernorm_k<<<MROWS, 256>>>(x, out, lnf_g, lnf_b);
}

// round 7
// speedup vs baseline: 3.2355x; 3.2355x over previous
#include <cuda_runtime.h>
#include <math.h>

// ---------------- problem constants ----------------
#define MROWS 4096            // B*T*N rows
#define DDIM  1152
#define NHEAD 16
#define HDIM  72
#define IDIM  4304
#define NPATCH 1024
#define KCONV 588             // 14*14*3
#define NLAYER 4

// ---------------- scratch (device globals; no allocations allowed) ----------
__device__ float g_x   [(size_t)MROWS*DDIM];
__device__ float g_h   [(size_t)MROWS*DDIM];
__device__ float g_q   [(size_t)MROWS*DDIM];
__device__ float g_k   [(size_t)MROWS*DDIM];
__device__ float g_v   [(size_t)MROWS*DDIM];
__device__ float g_attn[(size_t)MROWS*DDIM];
__device__ float g_mlp [(size_t)MROWS*IDIM];
__device__ float g_scor[(size_t)64*1024*1024];   // 64 (b,h) x 1024 x 1024
__device__ float g_col [(size_t)MROWS*KCONV];

// ---------------- im2col (stride == kernel, non-overlapping) ----------------
__global__ void im2col_k(const float* __restrict__ img, float* __restrict__ col) {
    int idx = blockIdx.x * blockDim.x + threadIdx.x;   // over 4096*588
    if (idx >= MROWS * KCONV) return;
    int p = idx / KCONV, j = idx % KCONV;
    int im = p >> 10;            // image 0..3
    int pr = (p >> 5) & 31;      // patch row
    int pc = p & 31;             // patch col
    int c  = j % 3;
    int t  = j / 3;
    int kx = t % 14, ky = t / 14;
    int y = pr * 14 + ky, x = pc * 14 + kx;
    col[idx] = img[(((size_t)im * 448 + y) * 448 + x) * 3 + c];
}

// ---------------- reductions ----------------
__device__ __forceinline__ float warp_sum(float v) {
    #pragma unroll
    for (int o = 16; o; o >>= 1) v += __shfl_xor_sync(0xffffffffu, v, o);
    return v;
}
__device__ __forceinline__ float warp_max(float v) {
    #pragma unroll
    for (int o = 16; o; o >>= 1) v = fmaxf(v, __shfl_xor_sync(0xffffffffu, v, o));
    return v;
}

// ---------------- layernorm: one block (256 thr) per row of length 1152 -----
__global__ void layernorm_k(const float* __restrict__ in, float* __restrict__ out,
                            const float* __restrict__ g, const float* __restrict__ b) {
    size_t row = blockIdx.x;
    const float* x = in + row * DDIM;
    float s = 0.f, s2 = 0.f;
    for (int i = threadIdx.x; i < DDIM; i += 256) { float v = x[i]; s += v; s2 += v * v; }
    __shared__ float sh0[8], sh1[8];
    s = warp_sum(s); s2 = warp_sum(s2);
    int w = threadIdx.x >> 5, l = threadIdx.x & 31;
    if (!l) { sh0[w] = s; sh1[w] = s2; }
    __syncthreads();
    if (w == 0) {
        float a = (l < 8) ? sh0[l] : 0.f;
        float c = (l < 8) ? sh1[l] : 0.f;
        a = warp_sum(a); c = warp_sum(c);
        if (!l) { sh0[0] = a; sh1[0] = c; }
    }
    __syncthreads();
    float mu  = sh0[0] * (1.f / DDIM);
    float var = sh1[0] * (1.f / DDIM) - mu * mu;
    float inv = rsqrtf(var + 1e-6f);
    float* o = out + row * DDIM;
    for (int i = threadIdx.x; i < DDIM; i += 256)
        o[i] = (x[i] - mu) * inv * g[i] + b[i];
}

// ---------------- softmax: one block (256 thr) per row of length 1024 -------
__global__ void softmax_k(float* __restrict__ s) {
    size_t row = blockIdx.x;
    float* p = s + row * 1024;
    __shared__ float sh[8];
    int w = threadIdx.x >> 5, l = threadIdx.x & 31;

    float mx = -1e30f;
    for (int i = threadIdx.x; i < 1024; i += 256) mx = fmaxf(mx, p[i]);
    mx = warp_max(mx);
    if (!l) sh[w] = mx;
    __syncthreads();
    if (w == 0) { float a = (l < 8) ? sh[l] : -1e30f; a = warp_max(a); if (!l) sh[0] = a; }
    __syncthreads();
    mx = sh[0];
    __syncthreads();

    float sum = 0.f;
    for (int i = threadIdx.x; i < 1024; i += 256) {
        float e = __expf(p[i] - mx);
        p[i] = e; sum += e;
    }
    sum = warp_sum(sum);
    if (!l) sh[w] = sum;
    __syncthreads();
    if (w == 0) { float a = (l < 8) ? sh[l] : 0.f; a = warp_sum(a); if (!l) sh[0] = a; }
    __syncthreads();
    float inv = 1.f / sh[0];
    for (int i = threadIdx.x; i < 1024; i += 256) p[i] *= inv;
}

// ---------------- tf32 tensor-core GEMM ------------------------------------
// C[M,N] = alpha * A[M,K] * op(B) (+bias[n]) (+posemb) (gelu) (+resid)
// Block tile 128x128x16, 8 warps (2x4), warp tile 64x32 via m16n8k8 tf32 mma.
// batch_mode: 0 none; 1 scores (A=Q,B=K per (b,h), C per z);
//             2 PV (A=probs per z, B=V per (b,h), C per (b,h))
#define BM 128
#define BN 128
#define BK 16
#define SPAD 136
#define FLAG_GELU 1

__device__ __forceinline__ unsigned f2tf32(float x) {
    unsigned u;
    asm("cvt.rna.tf32.f32 %0, %1;" : "=r"(u) : "f"(x));
    return u;
}

__device__ __forceinline__ void mma_tf32(float* c, const unsigned* a, const unsigned* b) {
    asm volatile(
        "mma.sync.aligned.m16n8k8.row.col.f32.tf32.tf32.f32 "
        "{%0,%1,%2,%3}, {%4,%5,%6,%7}, {%8,%9}, {%0,%1,%2,%3};\n"
        : "+f"(c[0]), "+f"(c[1]), "+f"(c[2]), "+f"(c[3])
        : "r"(a[0]), "r"(a[1]), "r"(a[2]), "r"(a[3]), "r"(b[0]), "r"(b[1]));
}

template<bool TRANSB>
__global__ void __launch_bounds__(256)
tgemm_k(const float* __restrict__ A, const float* __restrict__ B, float* __restrict__ C,
        int M, int N, int K, int lda, int ldb, int ldc,
        const float* __restrict__ bias, const float* __restrict__ resid,
        const float* __restrict__ posemb, float alpha, int flags, int bmode) {
    int z = blockIdx.z;
    if (bmode == 1) {
        int bb = z >> 4, hh = z & 15;
        size_t qk = (size_t)bb * 1024 * DDIM + (size_t)hh * HDIM;
        A += qk; B += qk; C += (size_t)z * 1024 * 1024;
    } else if (bmode == 2) {
        int bb = z >> 4, hh = z & 15;
        size_t vo = (size_t)bb * 1024 * DDIM + (size_t)hh * HDIM;
        A += (size_t)z * 1024 * 1024; B += vo; C += vo;
        if (resid) resid += vo;
    }

    __shared__ unsigned As[2][BK][SPAD];
    __shared__ unsigned Bs[2][BK][SPAD];

    int bm = blockIdx.y * BM, bn = blockIdx.x * BN;
    int tid = threadIdx.x;
    int lane = tid & 31, wid = tid >> 5;
    int wm = (wid & 1) * 64;        // warp m offset (2 warps in m)
    int wn = (wid >> 1) * 32;       // warp n offset (4 warps in n)
    int grp = lane >> 2, tig = lane & 3;

    // global-load thread mapping
    int ar  = tid >> 1, ac  = (tid & 1) * 4;   // A: 128 rows x (2 x float4 in k)
    int brr = tid >> 5, bcc = (tid & 31) * 4;  // B (no trans): 2x(8 k-rows) x float4 in n
    int tn  = tid >> 1, tk  = (tid & 1) * 4;   // B (trans): 128 n-rows x (2 x float4 in k)

    float4 aReg[2], bReg[2];

    auto ldTiles = [&](int k0) {
        #pragma unroll
        for (int h = 0; h < 2; h++) {
            int gk = k0 + ac + h * 8;
            aReg[h] = (gk < K) ? *(const float4*)(A + (size_t)(bm + ar) * lda + gk)
                               : make_float4(0.f, 0.f, 0.f, 0.f);
        }
        if (!TRANSB) {
            #pragma unroll
            for (int h = 0; h < 2; h++) {
                int gk = k0 + brr + h * 8;
                int gn = bn + bcc;
                bReg[h] = (gk < K && gn < N)
                          ? *(const float4*)(B + (size_t)gk * ldb + gn)
                          : make_float4(0.f, 0.f, 0.f, 0.f);
            }
        } else {
            #pragma unroll
            for (int h = 0; h < 2; h++) {
                int gk = k0 + tk + h * 8;
                int gn = bn + tn;
                bReg[h] = (gk < K && gn < N)
                          ? *(const float4*)(B + (size_t)gn * ldb + gk)
                          : make_float4(0.f, 0.f, 0.f, 0.f);
            }
        }
    };

    auto stTiles = [&](int buf) {
        #pragma unroll
        for (int h = 0; h < 2; h++) {
            As[buf][ac + h * 8 + 0][ar] = f2tf32(aReg[h].x);
            As[buf][ac + h * 8 + 1][ar] = f2tf32(aReg[h].y);
            As[buf][ac + h * 8 + 2][ar] = f2tf32(aReg[h].z);
            As[buf][ac + h * 8 + 3][ar] = f2tf32(aReg[h].w);
        }
        if (!TRANSB) {
            #pragma unroll
            for (int h = 0; h < 2; h++) {
                uint4 u;
                u.x = f2tf32(bReg[h].x); u.y = f2tf32(bReg[h].y);
                u.z = f2tf32(bReg[h].z); u.w = f2tf32(bReg[h].w);
                *(uint4*)&Bs[buf][brr + h * 8][bcc] = u;
            }
        } else {
            #pragma unroll
            for (int h = 0; h < 2; h++) {
                Bs[buf][tk + h * 8 + 0][tn] = f2tf32(bReg[h].x);
                Bs[buf][tk + h * 8 + 1][tn] = f2tf32(bReg[h].y);
                Bs[buf][tk + h * 8 + 2][tn] = f2tf32(bReg[h].z);
                Bs[buf][tk + h * 8 + 3][tn] = f2tf32(bReg[h].w);
            }
        }
    };

    float acc[4][4][4];
    #pragma unroll
    for (int i = 0; i < 4; i++)
        #pragma unroll
        for (int j = 0; j < 4; j++)
            #pragma unroll
            for (int r = 0; r < 4; r++) acc[i][j][r] = 0.f;

    int nk = (K + BK - 1) / BK;
    ldTiles(0);
    stTiles(0);
    __syncthreads();

    for (int kt = 0; kt < nk; kt++) {
        int cur = kt & 1;
        bool more = (kt + 1 < nk);
        if (more) ldTiles((kt + 1) * BK);

        #pragma unroll
        for (int ks = 0; ks < 2; ks++) {
            int kb = ks * 8;
            unsigned a[4][4], b[4][2];
            #pragma unroll
            for (int mt = 0; mt < 4; mt++) {
                int r0 = wm + mt * 16 + grp;
                a[mt][0] = As[cur][kb + tig    ][r0];
                a[mt][1] = As[cur][kb + tig    ][r0 + 8];
                a[mt][2] = As[cur][kb + tig + 4][r0];
                a[mt][3] = As[cur][kb + tig + 4][r0 + 8];
            }
            #pragma unroll
            for (int nt = 0; nt < 4; nt++) {
                int c0 = wn + nt * 8 + grp;
                b[nt][0] = Bs[cur][kb + tig    ][c0];
                b[nt][1] = Bs[cur][kb + tig + 4][c0];
            }
            #pragma unroll
            for (int mt = 0; mt < 4; mt++)
                #pragma unroll
                for (int nt = 0; nt < 4; nt++)
                    mma_tf32(acc[mt][nt], a[mt], b[nt]);
        }
        if (more) stTiles(cur ^ 1);
        __syncthreads();
    }

    // --- epilogue ---
    const float GC = 0.7978845608028654f;   // sqrt(2/pi)
    #pragma unroll
    for (int mt = 0; mt < 4; mt++) {
        #pragma unroll
        for (int nt = 0; nt < 4; nt++) {
            int gc = bn + wn + nt * 8 + 2 * tig;
            if (gc >= N) continue;
            #pragma unroll
            for (int half = 0; half < 2; half++) {
                int gm = bm + wm + mt * 16 + grp + half * 8;
                if (gm >= M) continue;
                float v0 = acc[mt][nt][half * 2 + 0] * alpha;
                float v1 = acc[mt][nt][half * 2 + 1] * alpha;
                if (bias)   { v0 += bias[gc]; v1 += bias[gc + 1]; }
                if (posemb) {
                    const float* pe = posemb + (size_t)(gm & (NPATCH - 1)) * DDIM;
                    v0 += pe[gc]; v1 += pe[gc + 1];
                }
                if (flags & FLAG_GELU) {
                    float t0 = v0, t1 = v1;
                    v0 = 0.5f * t0 * (1.f + tanhf(GC * (t0 + 0.044715f * t0 * t0 * t0)));
                    v1 = 0.5f * t1 * (1.f + tanhf(GC * (t1 + 0.044715f * t1 * t1 * t1)));
                }
                if (resid) {
                    v0 += resid[(size_t)gm * ldc + gc];
                    v1 += resid[(size_t)gm * ldc + gc + 1];
                }
                *(float2*)(C + (size_t)gm * ldc + gc) = make_float2(v0, v1);
            }
        }
    }
}

// ---------------- host-side helper ----------------
static void gemm(const float* A, const float* B, float* C,
                 int M, int N, int K, int lda, int ldb, int ldc,
                 const float* bias, const float* resid, const float* posemb,
                 float alpha, int flags, int bmode, int Z, bool transb) {
    dim3 grid((N + BN - 1) / BN, (M + BM - 1) / BM, Z);
    if (transb)
        tgemm_k<true ><<<grid, 256>>>(A, B, C, M, N, K, lda, ldb, ldc,
                                      bias, resid, posemb, alpha, flags, bmode);
    else
        tgemm_k<false><<<grid, 256>>>(A, B, C, M, N, K, lda, ldb, ldc,
                                      bias, resid, posemb, alpha, flags, bmode);
}

extern "C" void kernel_launch(void* const* d_in, const int* in_sizes, int n_in,
                              void* d_out, int out_size) {
    const float* images = (const float*)d_in[0];
    const float* conv_w = (const float*)d_in[1];
    const float* conv_b = (const float*)d_in[2];
    const float* posemb = (const float*)d_in[3];
    const float* ln1_g  = (const float*)d_in[4];
    const float* ln1_b  = (const float*)d_in[5];
    const float* Wq     = (const float*)d_in[6];
    const float* bq     = (const float*)d_in[7];
    const float* Wk     = (const float*)d_in[8];
    const float* bk     = (const float*)d_in[9];
    const float* Wv     = (const float*)d_in[10];
    const float* bv     = (const float*)d_in[11];
    const float* Wo     = (const float*)d_in[12];
    const float* bo     = (const float*)d_in[13];
    const float* ln2_g  = (const float*)d_in[14];
    const float* ln2_b  = (const float*)d_in[15];
    const float* W1     = (const float*)d_in[16];
    const float* b1     = (const float*)d_in[17];
    const float* W2     = (const float*)d_in[18];
    const float* b2     = (const float*)d_in[19];
    const float* lnf_g  = (const float*)d_in[20];
    const float* lnf_b  = (const float*)d_in[21];
    float* out = (float*)d_out;

    float *x, *h, *q, *k, *v, *attn, *mlp, *scor, *col;
    cudaGetSymbolAddress((void**)&x,    g_x);
    cudaGetSymbolAddress((void**)&h,    g_h);
    cudaGetSymbolAddress((void**)&q,    g_q);
    cudaGetSymbolAddress((void**)&k,    g_k);
    cudaGetSymbolAddress((void**)&v,    g_v);
    cudaGetSymbolAddress((void**)&attn, g_attn);
    cudaGetSymbolAddress((void**)&mlp,  g_mlp);
    cudaGetSymbolAddress((void**)&scor, g_scor);
    cudaGetSymbolAddress((void**)&col,  g_col);

    const float scale = 1.f / sqrtf((float)HDIM);

    // 1) patch embedding: im2col + GEMM (+conv_b +pos_emb) -> x
    {
        int tot = MROWS * KCONV;
        im2col_k<<<(tot + 255) / 256, 256>>>(images, col);
        gemm(col, conv_w, x, MROWS, DDIM, KCONV, KCONV, DDIM, DDIM,
             conv_b, nullptr, posemb, 1.f, 0, 0, 1, false);
    }

    // 2) transformer layers
    for (int l = 0; l < NLAYER; l++) {
        const float* wq = Wq + (size_t)l * DDIM * DDIM;
        const float* wk = Wk + (size_t)l * DDIM * DDIM;
        const float* wv = Wv + (size_t)l * DDIM * DDIM;
        const float* wo = Wo + (size_t)l * DDIM * DDIM;
        const float* w1 = W1 + (size_t)l * DDIM * IDIM;
        const float* w2 = W2 + (size_t)l * IDIM * DDIM;

        layernorm_k<<<MROWS, 256>>>(x, h, ln1_g + l * DDIM, ln1_b + l * DDIM);

        gemm(h, wq, q, MROWS, DDIM, DDIM, DDIM, DDIM, DDIM,
             bq + l * DDIM, nullptr, nullptr, 1.f, 0, 0, 1, false);
        gemm(h, wk, k, MROWS, DDIM, DDIM, DDIM, DDIM, DDIM,
             bk + l * DDIM, nullptr, nullptr, 1.f, 0, 0, 1, false);
        gemm(h, wv, v, MROWS, DDIM, DDIM, DDIM, DDIM, DDIM,
             bv + l * DDIM, nullptr, nullptr, 1.f, 0, 0, 1, false);

        // scores[z] = scale * Q K^T   (z = b*16 + h, 64 batches)
        gemm(q, k, scor, 1024, 1024, HDIM, DDIM, DDIM, 1024,
             nullptr, nullptr, nullptr, scale, 0, 1, 64, true);

        softmax_k<<<64 * 1024, 256>>>(scor);

        // attn[z] = P V
        gemm(scor, v, attn, 1024, HDIM, 1024, 1024, DDIM, DDIM,
             nullptr, nullptr, nullptr, 1.f, 0, 2, 64, false);

        // x = x + attn @ Wo + bo
        gemm(attn, wo, x, MROWS, DDIM, DDIM, DDIM, DDIM, DDIM,
             bo + l * DDIM, x, nullptr, 1.f, 0, 0, 1, false);

        layernorm_k<<<MROWS, 256>>>(x, h, ln2_g + l * DDIM, ln2_b + l * DDIM);

        // mlp = gelu(h @ W1 + b1)
        gemm(h, w1, mlp, MROWS, IDIM, DDIM, DDIM, IDIM, IDIM,
             b1 + l * IDIM, nullptr, nullptr, 1.f, FLAG_GELU, 0, 1, false);

        // x = x + mlp @ W2 + b2
        gemm(mlp, w2, x, MROWS, DDIM, IDIM, IDIM, DDIM, DDIM,
             b2 + l * DDIM, x, nullptr, 1.f, 0, 0, 1, false);
    }

    // 3) final layernorm -> d_out ([2,2,1024,1152] is row-major [4096,1152])
    layernorm_k<<<MROWS, 256>>>(x, out, lnf_g, lnf_b);
}

// round 8
// speedup vs baseline: 3.2422x; 1.0021x over previous
#include <cuda_runtime.h>
#include <math.h>

// ---------------- problem constants ----------------
#define MROWS 4096            // B*T*N rows
#define DDIM  1152
#define NHEAD 16
#define HDIM  72
#define IDIM  4304
#define NPATCH 1024
#define KCONV 588             // 14*14*3
#define NLAYER 4

// ---------------- scratch (device globals; no allocations allowed) ----------
__device__ float g_x   [(size_t)MROWS*DDIM];
__device__ float g_h   [(size_t)MROWS*DDIM];
__device__ float g_q   [(size_t)MROWS*DDIM];
__device__ float g_k   [(size_t)MROWS*DDIM];
__device__ float g_v   [(size_t)MROWS*DDIM];
__device__ float g_attn[(size_t)MROWS*DDIM];
__device__ float g_mlp [(size_t)MROWS*IDIM];
__device__ float g_scor[(size_t)64*1024*1024];   // 64 (b,h) x 1024 x 1024
__device__ float g_col [(size_t)MROWS*KCONV];

// ---------------- im2col (stride == kernel, non-overlapping) ----------------
__global__ void im2col_k(const float* __restrict__ img, float* __restrict__ col) {
    int idx = blockIdx.x * blockDim.x + threadIdx.x;   // over 4096*588
    if (idx >= MROWS * KCONV) return;
    int p = idx / KCONV, j = idx % KCONV;
    int im = p >> 10;            // image 0..3
    int pr = (p >> 5) & 31;      // patch row
    int pc = p & 31;             // patch col
    int c  = j % 3;
    int t  = j / 3;
    int kx = t % 14, ky = t / 14;
    int y = pr * 14 + ky, x = pc * 14 + kx;
    col[idx] = img[(((size_t)im * 448 + y) * 448 + x) * 3 + c];
}

// ---------------- reductions ----------------
__device__ __forceinline__ float warp_sum(float v) {
    #pragma unroll
    for (int o = 16; o; o >>= 1) v += __shfl_xor_sync(0xffffffffu, v, o);
    return v;
}
__device__ __forceinline__ float warp_max(float v) {
    #pragma unroll
    for (int o = 16; o; o >>= 1) v = fmaxf(v, __shfl_xor_sync(0xffffffffu, v, o));
    return v;
}

// ---------------- layernorm: one block (256 thr) per row of length 1152 -----
__global__ void layernorm_k(const float* __restrict__ in, float* __restrict__ out,
                            const float* __restrict__ g, const float* __restrict__ b) {
    size_t row = blockIdx.x;
    const float* x = in + row * DDIM;
    float s = 0.f, s2 = 0.f;
    for (int i = threadIdx.x; i < DDIM; i += 256) { float v = x[i]; s += v; s2 += v * v; }
    __shared__ float sh0[8], sh1[8];
    s = warp_sum(s); s2 = warp_sum(s2);
    int w = threadIdx.x >> 5, l = threadIdx.x & 31;
    if (!l) { sh0[w] = s; sh1[w] = s2; }
    __syncthreads();
    if (w == 0) {
        float a = (l < 8) ? sh0[l] : 0.f;
        float c = (l < 8) ? sh1[l] : 0.f;
        a = warp_sum(a); c = warp_sum(c);
        if (!l) { sh0[0] = a; sh1[0] = c; }
    }
    __syncthreads();
    float mu  = sh0[0] * (1.f / DDIM);
    float var = sh1[0] * (1.f / DDIM) - mu * mu;
    float inv = rsqrtf(var + 1e-6f);
    float* o = out + row * DDIM;
    for (int i = threadIdx.x; i < DDIM; i += 256)
        o[i] = (x[i] - mu) * inv * g[i] + b[i];
}

// ---------------- softmax: one block (256 thr) per row of length 1024 -------
__global__ void softmax_k(float* __restrict__ s) {
    size_t row = blockIdx.x;
    float* p = s + row * 1024;
    __shared__ float sh[8];
    int w = threadIdx.x >> 5, l = threadIdx.x & 31;

    float mx = -1e30f;
    for (int i = threadIdx.x; i < 1024; i += 256) mx = fmaxf(mx, p[i]);
    mx = warp_max(mx);
    if (!l) sh[w] = mx;
    __syncthreads();
    if (w == 0) { float a = (l < 8) ? sh[l] : -1e30f; a = warp_max(a); if (!l) sh[0] = a; }
    __syncthreads();
    mx = sh[0];
    __syncthreads();

    float sum = 0.f;
    for (int i = threadIdx.x; i < 1024; i += 256) {
        float e = __expf(p[i] - mx);
        p[i] = e; sum += e;
    }
    sum = warp_sum(sum);
    if (!l) sh[w] = sum;
    __syncthreads();
    if (w == 0) { float a = (l < 8) ? sh[l] : 0.f; a = warp_sum(a); if (!l) sh[0] = a; }
    __syncthreads();
    float inv = 1.f / sh[0];
    for (int i = threadIdx.x; i < 1024; i += 256) p[i] *= inv;
}

// ---------------- tf32 tensor-core GEMM ------------------------------------
// C[M,N] = alpha * A[M,K] * op(B) (+bias[n]) (+posemb) (gelu) (+resid)
// Block tile 128x128x16, 8 warps (2x4), warp tile 64x32 via m16n8k8 tf32 mma.
// batch_mode: 0 none; 1 scores (A=Q,B=K per (b,h), C per z);
//             2 PV (A=probs per z, B=V per (b,h), C per (b,h))
#define BM 128
#define BN 128
#define BK 16
#define SPAD 136
#define FLAG_GELU 1

__device__ __forceinline__ unsigned f2tf32(float x) {
    unsigned u;
    asm("cvt.rna.tf32.f32 %0, %1;" : "=r"(u) : "f"(x));
    return u;
}

__device__ __forceinline__ void mma_tf32(float* c, const unsigned* a, const unsigned* b) {
    asm volatile(
        "mma.sync.aligned.m16n8k8.row.col.f32.tf32.tf32.f32 "
        "{%0,%1,%2,%3}, {%4,%5,%6,%7}, {%8,%9}, {%0,%1,%2,%3};\n"
        : "+f"(c[0]), "+f"(c[1]), "+f"(c[2]), "+f"(c[3])
        : "r"(a[0]), "r"(a[1]), "r"(a[2]), "r"(a[3]), "r"(b[0]), "r"(b[1]));
}

template<bool TRANSB>
__global__ void __launch_bounds__(256)
tgemm_k(const float* __restrict__ A, const float* __restrict__ B, float* __restrict__ C,
        int M, int N, int K, int lda, int ldb, int ldc,
        const float* __restrict__ bias, const float* __restrict__ resid,
        const float* __restrict__ posemb, float alpha, int flags, int bmode) {
    int z = blockIdx.z;
    if (bmode == 1) {
        int bb = z >> 4, hh = z & 15;
        size_t qk = (size_t)bb * 1024 * DDIM + (size_t)hh * HDIM;
        A += qk; B += qk; C += (size_t)z * 1024 * 1024;
    } else if (bmode == 2) {
        int bb = z >> 4, hh = z & 15;
        size_t vo = (size_t)bb * 1024 * DDIM + (size_t)hh * HDIM;
        A += (size_t)z * 1024 * 1024; B += vo; C += vo;
        if (resid) resid += vo;
    }

    __shared__ unsigned As[2][BK][SPAD];
    __shared__ unsigned Bs[2][BK][SPAD];

    int bm = blockIdx.y * BM, bn = blockIdx.x * BN;
    int tid = threadIdx.x;
    int lane = tid & 31, wid = tid >> 5;
    int wm = (wid & 1) * 64;        // warp m offset (2 warps in m)
    int wn = (wid >> 1) * 32;       // warp n offset (4 warps in n)
    int grp = lane >> 2, tig = lane & 3;

    // global-load thread mapping
    int ar  = tid >> 1, ac  = (tid & 1) * 4;   // A: 128 rows x (2 x float4 in k)
    int brr = tid >> 5, bcc = (tid & 31) * 4;  // B (no trans): 2x(8 k-rows) x float4 in n
    int tn  = tid >> 1, tk  = (tid & 1) * 4;   // B (trans): 128 n-rows x (2 x float4 in k)

    float4 aReg[2], bReg[2];

    auto ldTiles = [&](int k0) {
        #pragma unroll
        for (int h = 0; h < 2; h++) {
            int gk = k0 + ac + h * 8;
            aReg[h] = (gk < K) ? *(const float4*)(A + (size_t)(bm + ar) * lda + gk)
                               : make_float4(0.f, 0.f, 0.f, 0.f);
        }
        if (!TRANSB) {
            #pragma unroll
            for (int h = 0; h < 2; h++) {
                int gk = k0 + brr + h * 8;
                int gn = bn + bcc;
                bReg[h] = (gk < K && gn < N)
                          ? *(const float4*)(B + (size_t)gk * ldb + gn)
                          : make_float4(0.f, 0.f, 0.f, 0.f);
            }
        } else {
            #pragma unroll
            for (int h = 0; h < 2; h++) {
                int gk = k0 + tk + h * 8;
                int gn = bn + tn;
                bReg[h] = (gk < K && gn < N)
                          ? *(const float4*)(B + (size_t)gn * ldb + gk)
                          : make_float4(0.f, 0.f, 0.f, 0.f);
            }
        }
    };

    auto stTiles = [&](int buf) {
        #pragma unroll
        for (int h = 0; h < 2; h++) {
            As[buf][ac + h * 8 + 0][ar] = f2tf32(aReg[h].x);
            As[buf][ac + h * 8 + 1][ar] = f2tf32(aReg[h].y);
            As[buf][ac + h * 8 + 2][ar] = f2tf32(aReg[h].z);
            As[buf][ac + h * 8 + 3][ar] = f2tf32(aReg[h].w);
        }
        if (!TRANSB) {
            #pragma unroll
            for (int h = 0; h < 2; h++) {
                uint4 u;
                u.x = f2tf32(bReg[h].x); u.y = f2tf32(bReg[h].y);
                u.z = f2tf32(bReg[h].z); u.w = f2tf32(bReg[h].w);
                *(uint4*)&Bs[buf][brr + h * 8][bcc] = u;
            }
        } else {
            #pragma unroll
            for (int h = 0; h < 2; h++) {
                Bs[buf][tk + h * 8 + 0][tn] = f2tf32(bReg[h].x);
                Bs[buf][tk + h * 8 + 1][tn] = f2tf32(bReg[h].y);
                Bs[buf][tk + h * 8 + 2][tn] = f2tf32(bReg[h].z);
                Bs[buf][tk + h * 8 + 3][tn] = f2tf32(bReg[h].w);
            }
        }
    };

    float acc[4][4][4];
    #pragma unroll
    for (int i = 0; i < 4; i++)
        #pragma unroll
        for (int j = 0; j < 4; j++)
            #pragma unroll
            for (int r = 0; r < 4; r++) acc[i][j][r] = 0.f;

    int nk = (K + BK - 1) / BK;
    ldTiles(0);
    stTiles(0);
    __syncthreads();

    for (int kt = 0; kt < nk; kt++) {
        int cur = kt & 1;
        bool more = (kt + 1 < nk);
        if (more) ldTiles((kt + 1) * BK);

        #pragma unroll
        for (int ks = 0; ks < 2; ks++) {
            int kb = ks * 8;
            unsigned a[4][4], b[4][2];
            #pragma unroll
            for (int mt = 0; mt < 4; mt++) {
                int r0 = wm + mt * 16 + grp;
                a[mt][0] = As[cur][kb + tig    ][r0];
                a[mt][1] = As[cur][kb + tig    ][r0 + 8];
                a[mt][2] = As[cur][kb + tig + 4][r0];
                a[mt][3] = As[cur][kb + tig + 4][r0 + 8];
            }
            #pragma unroll
            for (int nt = 0; nt < 4; nt++) {
                int c0 = wn + nt * 8 + grp;
                b[nt][0] = Bs[cur][kb + tig    ][c0];
                b[nt][1] = Bs[cur][kb + tig + 4][c0];
            }
            #pragma unroll
            for (int mt = 0; mt < 4; mt++)
                #pragma unroll
                for (int nt = 0; nt < 4; nt++)
                    mma_tf32(acc[mt][nt], a[mt], b[nt]);
        }
        if (more) stTiles(cur ^ 1);
        __syncthreads();
    }

    // --- epilogue ---
    const float GC = 0.7978845608028654f;   // sqrt(2/pi)
    #pragma unroll
    for (int mt = 0; mt < 4; mt++) {
        #pragma unroll
        for (int nt = 0; nt < 4; nt++) {
            int gc = bn + wn + nt * 8 + 2 * tig;
            if (gc >= N) continue;
            #pragma unroll
            for (int half = 0; half < 2; half++) {
                int gm = bm + wm + mt * 16 + grp + half * 8;
                if (gm >= M) continue;
                float v0 = acc[mt][nt][half * 2 + 0] * alpha;
                float v1 = acc[mt][nt][half * 2 + 1] * alpha;
                if (bias)   { v0 += bias[gc]; v1 += bias[gc + 1]; }
                if (posemb) {
                    const float* pe = posemb + (size_t)(gm & (NPATCH - 1)) * DDIM;
                    v0 += pe[gc]; v1 += pe[gc + 1];
                }
                if (flags & FLAG_GELU) {
                    float t0 = v0, t1 = v1;
                    v0 = 0.5f * t0 * (1.f + tanhf(GC * (t0 + 0.044715f * t0 * t0 * t0)));
                    v1 = 0.5f * t1 * (1.f + tanhf(GC * (t1 + 0.044715f * t1 * t1 * t1)));
                }
                if (resid) {
                    v0 += resid[(size_t)gm * ldc + gc];
                    v1 += resid[(size_t)gm * ldc + gc + 1];
                }
                *(float2*)(C + (size_t)gm * ldc + gc) = make_float2(v0, v1);
            }
        }
    }
}

// ---------------- host-side helper ----------------
static void gemm(const float* A, const float* B, float* C,
                 int M, int N, int K, int lda, int ldb, int ldc,
                 const float* bias, const float* resid, const float* posemb,
                 float alpha, int flags, int bmode, int Z, bool transb) {
    dim3 grid((N + BN - 1) / BN, (M + BM - 1) / BM, Z);
    if (transb)
        tgemm_k<true ><<<grid, 256>>>(A, B, C, M, N, K, lda, ldb, ldc,
                                      bias, resid, posemb, alpha, flags, bmode);
    else
        tgemm_k<false><<<grid, 256>>>(A, B, C, M, N, K, lda, ldb, ldc,
                                      bias, resid, posemb, alpha, flags, bmode);
}

extern "C" void kernel_launch(void* const* d_in, const int* in_sizes, int n_in,
                              void* d_out, int out_size) {
    const float* images = (const float*)d_in[0];
    const float* conv_w = (const float*)d_in[1];
    const float* conv_b = (const float*)d_in[2];
    const float* posemb = (const float*)d_in[3];
    const float* ln1_g  = (const float*)d_in[4];
    const float* ln1_b  = (const float*)d_in[5];
    const float* Wq     = (const float*)d_in[6];
    const float* bq     = (const float*)d_in[7];
    const float* Wk     = (const float*)d_in[8];
    const float* bk     = (const float*)d_in[9];
    const float* Wv     = (const float*)d_in[10];
    const float* bv     = (const float*)d_in[11];
    const float* Wo     = (const float*)d_in[12];
    const float* bo     = (const float*)d_in[13];
    const float* ln2_g  = (const float*)d_in[14];
    const float* ln2_b  = (const float*)d_in[15];
    const float* W1     = (const float*)d_in[16];
    const float* b1     = (const float*)d_in[17];
    const float* W2     = (const float*)d_in[18];
    const float* b2     = (const float*)d_in[19];
    const float* lnf_g  = (const float*)d_in[20];
    const float* lnf_b  = (const float*)d_in[21];
    float* out = (float*)d_out;

    float *x, *h, *q, *k, *v, *attn, *mlp, *scor, *col;
    cudaGetSymbolAddress((void**)&x,    g_x);
    cudaGetSymbolAddress((void**)&h,    g_h);
    cudaGetSymbolAddress((void**)&q,    g_q);
    cudaGetSymbolAddress((void**)&k,    g_k);
    cudaGetSymbolAddress((void**)&v,    g_v);
    cudaGetSymbolAddress((void**)&attn, g_attn);
    cudaGetSymbolAddress((void**)&mlp,  g_mlp);
    cudaGetSymbolAddress((void**)&scor, g_scor);
    cudaGetSymbolAddress((void**)&col,  g_col);

    const float scale = 1.f / sqrtf((float)HDIM);

    // 1) patch embedding: im2col + GEMM (+conv_b +pos_emb) -> x
    {
        int tot = MROWS * KCONV;
        im2col_k<<<(tot + 255) / 256, 256>>>(images, col);
        gemm(col, conv_w, x, MROWS, DDIM, KCONV, KCONV, DDIM, DDIM,
             conv_b, nullptr, posemb, 1.f, 0, 0, 1, false);
    }

    // 2) transformer layers
    for (int l = 0; l < NLAYER; l++) {
        const float* wq = Wq + (size_t)l * DDIM * DDIM;
        const float* wk = Wk + (size_t)l * DDIM * DDIM;
        const float* wv = Wv + (size_t)l * DDIM * DDIM;
        const float* wo = Wo + (size_t)l * DDIM * DDIM;
        const float* w1 = W1 + (size_t)l * DDIM * IDIM;
        const float* w2 = W2 + (size_t)l * IDIM * DDIM;

        layernorm_k<<<MROWS, 256>>>(x, h, ln1_g + l * DDIM, ln1_b + l * DDIM);

        gemm(h, wq, q, MROWS, DDIM, DDIM, DDIM, DDIM, DDIM,
             bq + l * DDIM, nullptr, nullptr, 1.f, 0, 0, 1, false);
        gemm(h, wk, k, MROWS, DDIM, DDIM, DDIM, DDIM, DDIM,
             bk + l * DDIM, nullptr, nullptr, 1.f, 0, 0, 1, false);
        gemm(h, wv, v, MROWS, DDIM, DDIM, DDIM, DDIM, DDIM,
             bv + l * DDIM, nullptr, nullptr, 1.f, 0, 0, 1, false);

        // scores[z] = scale * Q K^T   (z = b*16 + h, 64 batches)
        gemm(q, k, scor, 1024, 1024, HDIM, DDIM, DDIM, 1024,
             nullptr, nullptr, nullptr, scale, 0, 1, 64, true);

        softmax_k<<<64 * 1024, 256>>>(scor);

        // attn[z] = P V
        gemm(scor, v, attn, 1024, HDIM, 1024, 1024, DDIM, DDIM,
             nullptr, nullptr, nullptr, 1.f, 0, 2, 64, false);

        // x = x + attn @ Wo + bo
        gemm(attn, wo, x, MROWS, DDIM, DDIM, DDIM, DDIM, DDIM,
             bo + l * DDIM, x, nullptr, 1.f, 0, 0, 1, false);

        layernorm_k<<<MROWS, 256>>>(x, h, ln2_g + l * DDIM, ln2_b + l * DDIM);

        // mlp = gelu(h @ W1 + b1)
        gemm(h, w1, mlp, MROWS, IDIM, DDIM, DDIM, IDIM, IDIM,
             b1 + l * IDIM, nullptr, nullptr, 1.f, FLAG_GELU, 0, 1, false);

        // x = x + mlp @ W2 + b2
        gemm(mlp, w2, x, MROWS, DDIM, IDIM, IDIM, DDIM, DDIM,
             b2 + l * DDIM, x, nullptr, 1.f, 0, 0, 1, false);
    }

    // 3) final layernorm -> d_out ([2,2,1024,1152] is row-major [4096,1152])
    layernorm_k<<<MROWS, 256>>>(x, out, lnf_g, lnf_b);
}